// round 1
// baseline (speedup 1.0000x reference)
#include <cuda_runtime.h>
#include <cuda_bf16.h>
#include <math.h>

#define NN 30000
#define EE 480000
#define DD 128

// ---------------- static device scratch (no allocation allowed) ----------------
__device__ float g_z[NN * DD];        // z = h @ W^T
__device__ float g_hout[NN * DD];     // aggregated output pre-BN
__device__ int   g_counts[NN];        // in-degree histogram
__device__ int   g_cursor[NN];        // scatter cursors
__device__ int   g_offsets[NN + 1];   // CSR row offsets (by dst)
__device__ int   g_srcs[EE];          // src node ids sorted by dst
__device__ float g_stats[2 * DD];     // [0:128) sum, [128:256) sumsq

// ---------------- zero init ----------------
__global__ void zero_kernel() {
    int i = blockIdx.x * 256 + threadIdx.x;
    if (i < NN) { g_counts[i] = 0; g_cursor[i] = 0; }
    if (i < 2 * DD) g_stats[i] = 0.f;
}

// ---------------- GEMM: z[n][o] = sum_k h[n][k] * W[o][k] ----------------
// block: 256 threads, computes 64 rows x 128 cols
__global__ void gemm_kernel(const float* __restrict__ h, const float* __restrict__ W) {
    __shared__ float As[64][33];
    __shared__ float Bs[128][33];
    int t = threadIdx.x;
    int tx = t & 31;        // 0..31 -> col base
    int ty = t >> 5;        // 0..7  -> row group
    int rowBase = blockIdx.x * 64;

    float acc[8][4];
#pragma unroll
    for (int i = 0; i < 8; i++)
#pragma unroll
        for (int j = 0; j < 4; j++) acc[i][j] = 0.f;

    for (int kc = 0; kc < DD; kc += 32) {
#pragma unroll
        for (int l = 0; l < 8; l++) {           // 64x32 A tile
            int lin = t + 256 * l;
            int r = lin >> 5, kk = lin & 31;
            int row = rowBase + r;
            As[r][kk] = (row < NN) ? h[row * DD + kc + kk] : 0.f;
        }
#pragma unroll
        for (int l = 0; l < 16; l++) {          // 128x32 B tile
            int lin = t + 256 * l;
            int r = lin >> 5, kk = lin & 31;
            Bs[r][kk] = W[r * DD + kc + kk];
        }
        __syncthreads();
#pragma unroll
        for (int kk = 0; kk < 32; kk++) {
            float a[8], b[4];
#pragma unroll
            for (int i = 0; i < 8; i++) a[i] = As[ty + 8 * i][kk];
#pragma unroll
            for (int j = 0; j < 4; j++) b[j] = Bs[tx + 32 * j][kk];
#pragma unroll
            for (int i = 0; i < 8; i++)
#pragma unroll
                for (int j = 0; j < 4; j++) acc[i][j] = fmaf(a[i], b[j], acc[i][j]);
        }
        __syncthreads();
    }
#pragma unroll
    for (int i = 0; i < 8; i++) {
        int row = rowBase + ty + 8 * i;
        if (row < NN) {
#pragma unroll
            for (int j = 0; j < 4; j++) g_z[row * DD + tx + 32 * j] = acc[i][j];
        }
    }
}

// ---------------- histogram of dst ----------------
__global__ void hist_kernel(const int* __restrict__ dst) {
    int e = blockIdx.x * 256 + threadIdx.x;
    if (e < EE) atomicAdd(&g_counts[dst[e]], 1);
}

// ---------------- single-block exclusive scan of counts -> offsets ----------------
__global__ void scan_kernel() {
    __shared__ int wsum[32];
    int t = threadIdx.x;           // 1024 threads
    int lane = t & 31, warp = t >> 5;
    int carry = 0;                 // uniform across threads
    for (int base = 0; base < NN; base += 1024) {
        int idx = base + t;
        int x = (idx < NN) ? g_counts[idx] : 0;
        int v = x;
#pragma unroll
        for (int o = 1; o < 32; o <<= 1) {
            int y = __shfl_up_sync(0xFFFFFFFFu, v, o);
            if (lane >= o) v += y;
        }
        if (lane == 31) wsum[warp] = v;
        __syncthreads();
        if (warp == 0) {
            int w = wsum[lane];
#pragma unroll
            for (int o = 1; o < 32; o <<= 1) {
                int y = __shfl_up_sync(0xFFFFFFFFu, w, o);
                if (lane >= o) w += y;
            }
            wsum[lane] = w;
        }
        __syncthreads();
        int incl = v + (warp ? wsum[warp - 1] : 0);
        int total = wsum[31];
        if (idx < NN) g_offsets[idx] = carry + incl - x;   // exclusive
        carry += total;
        __syncthreads();   // protect wsum for next iteration
    }
    if (t == 0) g_offsets[NN] = carry;
}

// ---------------- scatter edges into CSR order ----------------
__global__ void scatter_kernel(const int* __restrict__ src, const int* __restrict__ dst) {
    int e = blockIdx.x * 256 + threadIdx.x;
    if (e < EE) {
        int d = dst[e];
        int pos = g_offsets[d] + atomicAdd(&g_cursor[d], 1);
        g_srcs[pos] = src[e];
    }
}

// ---------------- per-dst softmax aggregation (one block per node) ----------------
__global__ void agg_kernel(const float* __restrict__ snorm) {
    int d = blockIdx.x;
    int c = threadIdx.x;           // channel 0..127
    int s0 = g_offsets[d];
    int s1 = g_offsets[d + 1];
    float zd = g_z[d * DD + c];
    float den = 0.f, acc = 0.f;
    __shared__ int ssrc[128];
    for (int base = s0; base < s1; base += 128) {
        int m = s1 - base; if (m > 128) m = 128;
        if (c < m) ssrc[c] = g_srcs[base + c];
        __syncthreads();
        for (int i = 0; i < m; i++) {
            float zs = g_z[ssrc[i] * DD + c];
            float w = __expf(zs * zd);      // no shift needed: |e| << 88
            den += w;
            acc = fmaf(w, zs, acc);
        }
        __syncthreads();
    }
    float h = (den > 0.f) ? (acc / den) * snorm[d] : 0.f;
    g_hout[d * DD + c] = h;
}

// ---------------- BN statistics (per-channel sum / sumsq) ----------------
__global__ void bnstats_kernel() {
    int c = threadIdx.x;           // 128 threads
    float s = 0.f, s2 = 0.f;
    for (int r = blockIdx.x; r < NN; r += gridDim.x) {
        float v = g_hout[r * DD + c];
        s += v;
        s2 = fmaf(v, v, s2);
    }
    atomicAdd(&g_stats[c], s);
    atomicAdd(&g_stats[DD + c], s2);
}

// ---------------- BN apply + ELU ----------------
__global__ void apply_kernel(const float* __restrict__ gamma,
                             const float* __restrict__ beta,
                             float* __restrict__ out) {
    int idx = blockIdx.x * 256 + threadIdx.x;
    if (idx >= NN * DD) return;
    int c = idx & (DD - 1);
    const float invN = 1.f / (float)NN;
    float mu = g_stats[c] * invN;
    float var = g_stats[DD + c] * invN - mu * mu;
    float rs = rsqrtf(var + 1e-5f);
    float v = (g_hout[idx] - mu) * rs * gamma[c] + beta[c];
    out[idx] = (v > 0.f) ? v : expm1f(v);
}

// ---------------- launch ----------------
extern "C" void kernel_launch(void* const* d_in, const int* in_sizes, int n_in,
                              void* d_out, int out_size) {
    const float* h      = (const float*)d_in[0];   // [N,128]
    const float* snorm  = (const float*)d_in[1];   // [N,1]
    const float* W      = (const float*)d_in[2];   // [128,128]
    const float* gamma  = (const float*)d_in[3];   // [128]
    const float* beta   = (const float*)d_in[4];   // [128]
    const int*   src    = (const int*)d_in[5];     // [E]
    const int*   dst    = (const int*)d_in[6];     // [E]
    float* out = (float*)d_out;

    zero_kernel<<<(NN + 255) / 256, 256>>>();
    gemm_kernel<<<(NN + 63) / 64, 256>>>(h, W);
    hist_kernel<<<(EE + 255) / 256, 256>>>(dst);
    scan_kernel<<<1, 1024>>>();
    scatter_kernel<<<(EE + 255) / 256, 256>>>(src, dst);
    agg_kernel<<<NN, 128>>>(snorm);
    bnstats_kernel<<<256, 128>>>();
    apply_kernel<<<(NN * DD + 255) / 256, 256>>>(gamma, beta, out);
}